// round 6
// baseline (speedup 1.0000x reference)
#include <cuda_runtime.h>
#include <cuda_bf16.h>

// x is [B=4096, T=512, D=4] batch_first; H=32
#define H        32
#define DIN      4
#define EPW      8          // batch elements per warp (4 pairs)
#define NWARPS   4
#define NTHREADS 128
#define ELB      (NWARPS * EPW)   // 32 elements per block
#define CHUNK    16
#define WPAD     36

typedef unsigned long long u64;

static __device__ __forceinline__ u64 pk2(float lo, float hi) {
    u64 r; asm("mov.b64 %0,{%1,%2};" : "=l"(r) : "f"(lo), "f"(hi)); return r;
}
static __device__ __forceinline__ void upk2(u64 v, float& lo, float& hi) {
    asm("mov.b64 {%0,%1},%2;" : "=f"(lo), "=f"(hi) : "l"(v));
}
static __device__ __forceinline__ u64 fma2(u64 a, u64 b, u64 c) {
    u64 d; asm("fma.rn.f32x2 %0,%1,%2,%3;" : "=l"(d) : "l"(a), "l"(b), "l"(c)); return d;
}
static __device__ __forceinline__ void dup4(float4 v, u64* o) {
    o[0] = pk2(v.x, v.x); o[1] = pk2(v.y, v.y);
    o[2] = pk2(v.z, v.z); o[3] = pk2(v.w, v.w);
}
static __device__ __forceinline__ float sigf(float x) {
    return 1.0f / (1.0f + __expf(-x));
}
static __device__ __forceinline__ float tanhfast(float x) {
    return 2.0f / (1.0f + __expf(-2.0f * x)) - 1.0f;
}

// smem (floats): wih0dup 1024 | whh0 4608 | wih1 4608 | whh1 4608 |
//                h1 4*256 | h2 4*256 | x 4*512
#define SM_FLOATS (1024 + 3 * 128 * WPAD + NWARPS * 256 * 2 + NWARPS * 512)
#define SM_BYTES  (SM_FLOATS * 4)

__global__ __launch_bounds__(NTHREADS, 1)
void lstm2_kernel(const float* __restrict__ x,
                  const float* __restrict__ Wih0, const float* __restrict__ Whh0,
                  const float* __restrict__ bih0, const float* __restrict__ bhh0,
                  const float* __restrict__ Wih1, const float* __restrict__ Whh1,
                  const float* __restrict__ bih1, const float* __restrict__ bhh1,
                  const float* __restrict__ Wout, const float* __restrict__ bout,
                  float* __restrict__ out, int T)
{
    extern __shared__ float sm[];
    float* s_wih0d = sm;                          // [128][4][2] dup'd
    float* s_whh0  = sm + 1024;                   // [128][36]
    float* s_wih1  = s_whh0 + 128 * WPAD;
    float* s_whh1  = s_wih1 + 128 * WPAD;
    float* s_h1    = s_whh1 + 128 * WPAD;         // [NWARPS][4][32][2]
    float* s_h2    = s_h1 + NWARPS * 256;
    float* s_x     = s_h2 + NWARPS * 256;         // [NWARPS][4][CHUNK][4][2]

    const int tid = threadIdx.x;
    const int w   = tid >> 5;
    const int j   = tid & 31;               // hidden unit owned by this lane
    const int eb  = (blockIdx.x * NWARPS + w) * EPW;
    const int T4  = T * DIN;

    // ---- stage weights (block-wide, once) ----
    for (int i = tid; i < 4096; i += NTHREADS) {
        int r = i >> 5, k = i & 31;
        s_whh0[r * WPAD + k] = Whh0[i];
        s_wih1[r * WPAD + k] = Wih1[i];
        s_whh1[r * WPAD + k] = Whh1[i];
    }
    for (int i = tid; i < 512; i += NTHREADS) {
        int r = i >> 2, d = i & 3;
        float v = Wih0[i];
        s_wih0d[r * 8 + d * 2]     = v;
        s_wih0d[r * 8 + d * 2 + 1] = v;
    }

    float* h1w = s_h1 + w * 256;
    float* h2w = s_h2 + w * 256;
    float* xw  = s_x  + w * 512;

    // zero h state (warp-private)
#pragma unroll
    for (int p = 0; p < 4; ++p) {
        *(float2*)(h1w + p * 64 + 2 * j) = make_float2(0.f, 0.f);
        *(float2*)(h2w + p * 64 + 2 * j) = make_float2(0.f, 0.f);
    }

    const int rg[4] = { j, 32 + j, 64 + j, 96 + j };  // i,f,g,o rows
    u64 b0d[4], b1d[4];
#pragma unroll
    for (int g = 0; g < 4; ++g) {
        float b0 = bih0[rg[g]] + bhh0[rg[g]];
        float b1 = bih1[rg[g]] + bhh1[rg[g]];
        b0d[g] = pk2(b0, b0);
        b1d[g] = pk2(b1, b1);
    }

    float2 c1[4], c2[4];
#pragma unroll
    for (int p = 0; p < 4; ++p) { c1[p] = make_float2(0.f, 0.f); c2[p] = make_float2(0.f, 0.f); }

    __syncthreads();

    for (int t = 0; t < T; ++t) {
        // ---- stage x chunk (pair-interleaved) ----
        if ((t & (CHUNK - 1)) == 0) {
            __syncwarp();
#pragma unroll
            for (int n = 0; n < CHUNK; ++n) {
                int i  = n * 32 + j;                       // [pr][tt][d][ei]
                int pr = i >> 7;
                int tt = (i >> 3) & (CHUNK - 1);
                int d  = (i >> 1) & 3;
                int ei = i & 1;
                int tg = t + tt;
                xw[i] = (tg < T)
                    ? x[(size_t)(eb + 2 * pr + ei) * T4 + tg * DIN + d] : 0.f;
            }
            __syncwarp();
        }
        const int ts = t & (CHUNK - 1);

        // ================= layer 0 =================
        u64 acc[4][4];
#pragma unroll
        for (int p = 0; p < 4; ++p)
#pragma unroll
            for (int g = 0; g < 4; ++g) acc[p][g] = b0d[g];

        {   // x contribution (weights pre-duplicated in smem)
            ulonglong2 wva[4], wvb[4];
#pragma unroll
            for (int g = 0; g < 4; ++g) {
                wva[g] = *(const ulonglong2*)(s_wih0d + rg[g] * 8);
                wvb[g] = *(const ulonglong2*)(s_wih0d + rg[g] * 8 + 4);
            }
#pragma unroll
            for (int p = 0; p < 4; ++p) {
                ulonglong2 xa = *(const ulonglong2*)(xw + p * 128 + ts * 8);
                ulonglong2 xb = *(const ulonglong2*)(xw + p * 128 + ts * 8 + 4);
#pragma unroll
                for (int g = 0; g < 4; ++g) {
                    acc[p][g] = fma2(wva[g].x, xa.x, acc[p][g]);
                    acc[p][g] = fma2(wva[g].y, xa.y, acc[p][g]);
                    acc[p][g] = fma2(wvb[g].x, xb.x, acc[p][g]);
                    acc[p][g] = fma2(wvb[g].y, xb.y, acc[p][g]);
                }
            }
        }
        // recurrent: Whh0 . h1_old
#pragma unroll 2
        for (int kk = 0; kk < 8; ++kk) {
            u64 wd[4][4];
            dup4(*(const float4*)(s_whh0 + rg[0] * WPAD + kk * 4), wd[0]);
            dup4(*(const float4*)(s_whh0 + rg[1] * WPAD + kk * 4), wd[1]);
            dup4(*(const float4*)(s_whh0 + rg[2] * WPAD + kk * 4), wd[2]);
            dup4(*(const float4*)(s_whh0 + rg[3] * WPAD + kk * 4), wd[3]);
#pragma unroll
            for (int p = 0; p < 4; ++p) {
                ulonglong2 ha = *(const ulonglong2*)(h1w + p * 64 + kk * 8);
                ulonglong2 hb = *(const ulonglong2*)(h1w + p * 64 + kk * 8 + 4);
#pragma unroll
                for (int g = 0; g < 4; ++g) {
                    acc[p][g] = fma2(wd[g][0], ha.x, acc[p][g]);
                    acc[p][g] = fma2(wd[g][1], ha.y, acc[p][g]);
                    acc[p][g] = fma2(wd[g][2], hb.x, acc[p][g]);
                    acc[p][g] = fma2(wd[g][3], hb.y, acc[p][g]);
                }
            }
        }
        // epilogue: activations + c/h update (lane-local, no shuffles)
#pragma unroll
        for (int p = 0; p < 4; ++p) {
            float ia, ib, fa, fb, ga, gb, oa, ob;
            upk2(acc[p][0], ia, ib); upk2(acc[p][1], fa, fb);
            upk2(acc[p][2], ga, gb); upk2(acc[p][3], oa, ob);
            float cx = fmaf(sigf(fa), c1[p].x, sigf(ia) * tanhfast(ga));
            float cy = fmaf(sigf(fb), c1[p].y, sigf(ib) * tanhfast(gb));
            c1[p].x = cx; c1[p].y = cy;
            *(float2*)(h1w + p * 64 + 2 * j) =
                make_float2(sigf(oa) * tanhfast(cx), sigf(ob) * tanhfast(cy));
        }
        __syncwarp();

        // ================= layer 1 =================
#pragma unroll
        for (int p = 0; p < 4; ++p)
#pragma unroll
            for (int g = 0; g < 4; ++g) acc[p][g] = b1d[g];

        // part A: Wih1 . h1_new
#pragma unroll 2
        for (int kk = 0; kk < 8; ++kk) {
            u64 wd[4][4];
            dup4(*(const float4*)(s_wih1 + rg[0] * WPAD + kk * 4), wd[0]);
            dup4(*(const float4*)(s_wih1 + rg[1] * WPAD + kk * 4), wd[1]);
            dup4(*(const float4*)(s_wih1 + rg[2] * WPAD + kk * 4), wd[2]);
            dup4(*(const float4*)(s_wih1 + rg[3] * WPAD + kk * 4), wd[3]);
#pragma unroll
            for (int p = 0; p < 4; ++p) {
                ulonglong2 ha = *(const ulonglong2*)(h1w + p * 64 + kk * 8);
                ulonglong2 hb = *(const ulonglong2*)(h1w + p * 64 + kk * 8 + 4);
#pragma unroll
                for (int g = 0; g < 4; ++g) {
                    acc[p][g] = fma2(wd[g][0], ha.x, acc[p][g]);
                    acc[p][g] = fma2(wd[g][1], ha.y, acc[p][g]);
                    acc[p][g] = fma2(wd[g][2], hb.x, acc[p][g]);
                    acc[p][g] = fma2(wd[g][3], hb.y, acc[p][g]);
                }
            }
        }
        // part B: Whh1 . h2_old
#pragma unroll 2
        for (int kk = 0; kk < 8; ++kk) {
            u64 wd[4][4];
            dup4(*(const float4*)(s_whh1 + rg[0] * WPAD + kk * 4), wd[0]);
            dup4(*(const float4*)(s_whh1 + rg[1] * WPAD + kk * 4), wd[1]);
            dup4(*(const float4*)(s_whh1 + rg[2] * WPAD + kk * 4), wd[2]);
            dup4(*(const float4*)(s_whh1 + rg[3] * WPAD + kk * 4), wd[3]);
#pragma unroll
            for (int p = 0; p < 4; ++p) {
                ulonglong2 ha = *(const ulonglong2*)(h2w + p * 64 + kk * 8);
                ulonglong2 hb = *(const ulonglong2*)(h2w + p * 64 + kk * 8 + 4);
#pragma unroll
                for (int g = 0; g < 4; ++g) {
                    acc[p][g] = fma2(wd[g][0], ha.x, acc[p][g]);
                    acc[p][g] = fma2(wd[g][1], ha.y, acc[p][g]);
                    acc[p][g] = fma2(wd[g][2], hb.x, acc[p][g]);
                    acc[p][g] = fma2(wd[g][3], hb.y, acc[p][g]);
                }
            }
        }
#pragma unroll
        for (int p = 0; p < 4; ++p) {
            float ia, ib, fa, fb, ga, gb, oa, ob;
            upk2(acc[p][0], ia, ib); upk2(acc[p][1], fa, fb);
            upk2(acc[p][2], ga, gb); upk2(acc[p][3], oa, ob);
            float cx = fmaf(sigf(fa), c2[p].x, sigf(ia) * tanhfast(ga));
            float cy = fmaf(sigf(fb), c2[p].y, sigf(ib) * tanhfast(gb));
            c2[p].x = cx; c2[p].y = cy;
            *(float2*)(h2w + p * 64 + 2 * j) =
                make_float2(sigf(oa) * tanhfast(cx), sigf(ob) * tanhfast(cy));
        }
        __syncwarp();
    }

    // ---- final projection out[b] = h2 . Wout + bout ----
    const float wj = Wout[j];
    const float bo = bout[0];
#pragma unroll
    for (int p = 0; p < 4; ++p) {
        float2 hv = *(float2*)(h2w + p * 64 + 2 * j);
        float va = hv.x * wj, vb = hv.y * wj;
#pragma unroll
        for (int off = 16; off; off >>= 1) {
            va += __shfl_xor_sync(0xffffffffu, va, off);
            vb += __shfl_xor_sync(0xffffffffu, vb, off);
        }
        if (j == 0) {
            out[eb + 2 * p]     = va + bo;
            out[eb + 2 * p + 1] = vb + bo;
        }
    }
}

extern "C" void kernel_launch(void* const* d_in, const int* in_sizes, int n_in,
                              void* d_out, int out_size)
{
    const float* x    = (const float*)d_in[0];
    const float* Wih0 = (const float*)d_in[1];
    const float* Whh0 = (const float*)d_in[2];
    const float* bih0 = (const float*)d_in[3];
    const float* bhh0 = (const float*)d_in[4];
    const float* Wih1 = (const float*)d_in[5];
    const float* Whh1 = (const float*)d_in[6];
    const float* bih1 = (const float*)d_in[7];
    const float* bhh1 = (const float*)d_in[8];
    const float* Wout = (const float*)d_in[9];
    const float* bout = (const float*)d_in[10];
    float* out = (float*)d_out;

    const int B = out_size;                 // 4096
    const int T = in_sizes[0] / (B * DIN);  // 512

    cudaFuncSetAttribute(lstm2_kernel,
                         cudaFuncAttributeMaxDynamicSharedMemorySize, SM_BYTES);
    lstm2_kernel<<<B / ELB, NTHREADS, SM_BYTES>>>(
        x, Wih0, Whh0, bih0, bhh0, Wih1, Whh1, bih1, bhh1, Wout, bout, out, T);
}

// round 8
// speedup vs baseline: 2.8176x; 2.8176x over previous
#include <cuda_runtime.h>
#include <cuda_bf16.h>

// x is [B=4096, T=512, D=4] batch_first; H=32
#define DIN      4
#define EPW      4          // batch elements per warp
#define NWARPS   8
#define NTHREADS 256
#define ELB      (NWARPS * EPW)   // 32 elements per block
#define CHUNK    16
#define WPAD     36         // padded weight row stride (floats); 144B -> conflict-free

typedef unsigned long long u64;

static __device__ __forceinline__ u64 pk2(float lo, float hi) {
    u64 r; asm("mov.b64 %0,{%1,%2};" : "=l"(r) : "f"(lo), "f"(hi)); return r;
}
static __device__ __forceinline__ void upk2(u64 v, float& lo, float& hi) {
    asm("mov.b64 {%0,%1},%2;" : "=f"(lo), "=f"(hi) : "l"(v));
}
static __device__ __forceinline__ u64 fma2(u64 a, u64 b, u64 c) {
    u64 d; asm("fma.rn.f32x2 %0,%1,%2,%3;" : "=l"(d) : "l"(a), "l"(b), "l"(c)); return d;
}
static __device__ __forceinline__ float sigf(float x) {
    return 1.0f / (1.0f + __expf(-x));
}
static __device__ __forceinline__ float tanhfast(float x) {
    return 2.0f / (1.0f + __expf(-2.0f * x)) - 1.0f;
}

// smem (floats): whh0 | wih1 | whh1 (128 x WPAD each) | h1 | h2 | xbuf
#define SM_FLOATS (3 * 128 * WPAD + 2 * NWARPS * EPW * 32 + NWARPS * EPW * CHUNK * 4)
#define SM_BYTES  (SM_FLOATS * 4)

__global__ __launch_bounds__(NTHREADS, 1)
void lstm2_kernel(const float* __restrict__ x,
                  const float* __restrict__ Wih0, const float* __restrict__ Whh0,
                  const float* __restrict__ bih0, const float* __restrict__ bhh0,
                  const float* __restrict__ Wih1, const float* __restrict__ Whh1,
                  const float* __restrict__ bih1, const float* __restrict__ bhh1,
                  const float* __restrict__ Wout, const float* __restrict__ bout,
                  float* __restrict__ out, int T)
{
    extern __shared__ float sm[];
    float* s_whh0 = sm;                           // [128][WPAD]
    float* s_wih1 = s_whh0 + 128 * WPAD;
    float* s_whh1 = s_wih1 + 128 * WPAD;
    float* s_h1   = s_whh1 + 128 * WPAD;          // [NWARPS][EPW][32]
    float* s_h2   = s_h1 + NWARPS * EPW * 32;
    float* s_x    = s_h2 + NWARPS * EPW * 32;     // [NWARPS][EPW][CHUNK][4]

    const int tid = threadIdx.x;
    const int w   = tid >> 5;
    const int j   = tid & 31;                // hidden unit owned by this lane
    const int eb  = (blockIdx.x * NWARPS + w) * EPW;
    const int T4  = T * DIN;

    // ---- stage recurrent/input weights into padded smem rows (once) ----
    for (int i = tid; i < 4096; i += NTHREADS) {
        int r = i >> 5, k = i & 31;
        s_whh0[r * WPAD + k] = Whh0[i];
        s_wih1[r * WPAD + k] = Wih1[i];
        s_whh1[r * WPAD + k] = Whh1[i];
    }

    float* h1w = s_h1 + w * (EPW * 32);
    float* h2w = s_h2 + w * (EPW * 32);
    float* xw  = s_x  + w * (EPW * CHUNK * 4);

#pragma unroll
    for (int e = 0; e < EPW; ++e) { h1w[e * 32 + j] = 0.f; h2w[e * 32 + j] = 0.f; }

    const int rg[4] = { j, 32 + j, 64 + j, 96 + j };  // i,f,g,o rows for unit j

    // layer0 input weights (4 floats per gate) + biases: register-resident
    u64 wi0[4][2], b0pk[4], b1pk[4];
#pragma unroll
    for (int g = 0; g < 4; ++g) {
        float4 wv = *(const float4*)(Wih0 + rg[g] * 4);
        wi0[g][0] = pk2(wv.x, wv.y);
        wi0[g][1] = pk2(wv.z, wv.w);
        b0pk[g] = pk2(bih0[rg[g]] + bhh0[rg[g]], 0.f);
        b1pk[g] = pk2(bih1[rg[g]] + bhh1[rg[g]], 0.f);
    }

    float c1[EPW], c2[EPW];
#pragma unroll
    for (int e = 0; e < EPW; ++e) { c1[e] = 0.f; c2[e] = 0.f; }

    __syncthreads();

    for (int t = 0; t < T; ++t) {
        // ---- stage x chunk (warp-private, natural layout) ----
        if ((t & (CHUNK - 1)) == 0) {
            __syncwarp();
#pragma unroll
            for (int n = 0; n < (EPW * CHUNK) / 32; ++n) {   // 2 float4s per lane
                int i  = n * 32 + j;           // float4 index: [el][tt]
                int el = i >> 4;
                int r  = i & (CHUNK - 1);
                int tg = t + r;
                float4 v = (tg < T)
                    ? *(const float4*)(x + (size_t)(eb + el) * T4 + tg * DIN)
                    : make_float4(0.f, 0.f, 0.f, 0.f);
                *(float4*)(xw + i * 4) = v;
            }
            __syncwarp();
        }
        const int ts = t & (CHUNK - 1);

        // ================= layer 0 =================
        u64 acc[EPW][4];
#pragma unroll
        for (int e = 0; e < EPW; ++e) {
            ulonglong2 xx = *(const ulonglong2*)(xw + e * CHUNK * 4 + ts * 4);
#pragma unroll
            for (int g = 0; g < 4; ++g) {
                u64 a = fma2(wi0[g][0], xx.x, b0pk[g]);
                acc[e][g] = fma2(wi0[g][1], xx.y, a);
            }
        }
#pragma unroll
        for (int kk = 0; kk < 8; ++kk) {
            ulonglong2 wd[4];
#pragma unroll
            for (int g = 0; g < 4; ++g)
                wd[g] = *(const ulonglong2*)(s_whh0 + rg[g] * WPAD + kk * 4);
#pragma unroll
            for (int e = 0; e < EPW; ++e) {
                ulonglong2 hh = *(const ulonglong2*)(h1w + e * 32 + kk * 4); // broadcast
#pragma unroll
                for (int g = 0; g < 4; ++g) {
                    acc[e][g] = fma2(wd[g].x, hh.x, acc[e][g]);
                    acc[e][g] = fma2(wd[g].y, hh.y, acc[e][g]);
                }
            }
        }
        __syncwarp();   // all h1_old reads done before overwriting
#pragma unroll
        for (int e = 0; e < EPW; ++e) {
            float lo, hi;
            upk2(acc[e][0], lo, hi); float gi_ = lo + hi;
            upk2(acc[e][1], lo, hi); float gf_ = lo + hi;
            upk2(acc[e][2], lo, hi); float gg_ = lo + hi;
            upk2(acc[e][3], lo, hi); float go_ = lo + hi;
            float c = fmaf(sigf(gf_), c1[e], sigf(gi_) * tanhfast(gg_));
            c1[e] = c;
            h1w[e * 32 + j] = sigf(go_) * tanhfast(c);
        }
        __syncwarp();   // h1_new visible to whole warp

        // ================= layer 1 =================
#pragma unroll
        for (int e = 0; e < EPW; ++e)
#pragma unroll
            for (int g = 0; g < 4; ++g) acc[e][g] = b1pk[g];
#pragma unroll
        for (int kk = 0; kk < 8; ++kk) {
            ulonglong2 wi[4], wh[4];
#pragma unroll
            for (int g = 0; g < 4; ++g) {
                wi[g] = *(const ulonglong2*)(s_wih1 + rg[g] * WPAD + kk * 4);
                wh[g] = *(const ulonglong2*)(s_whh1 + rg[g] * WPAD + kk * 4);
            }
#pragma unroll
            for (int e = 0; e < EPW; ++e) {
                ulonglong2 ha = *(const ulonglong2*)(h1w + e * 32 + kk * 4); // broadcast
                ulonglong2 hb = *(const ulonglong2*)(h2w + e * 32 + kk * 4); // broadcast
#pragma unroll
                for (int g = 0; g < 4; ++g) {
                    acc[e][g] = fma2(wi[g].x, ha.x, acc[e][g]);
                    acc[e][g] = fma2(wi[g].y, ha.y, acc[e][g]);
                    acc[e][g] = fma2(wh[g].x, hb.x, acc[e][g]);
                    acc[e][g] = fma2(wh[g].y, hb.y, acc[e][g]);
                }
            }
        }
        __syncwarp();   // all h2_old reads done before overwriting
#pragma unroll
        for (int e = 0; e < EPW; ++e) {
            float lo, hi;
            upk2(acc[e][0], lo, hi); float gi_ = lo + hi;
            upk2(acc[e][1], lo, hi); float gf_ = lo + hi;
            upk2(acc[e][2], lo, hi); float gg_ = lo + hi;
            upk2(acc[e][3], lo, hi); float go_ = lo + hi;
            float c = fmaf(sigf(gf_), c2[e], sigf(gi_) * tanhfast(gg_));
            c2[e] = c;
            h2w[e * 32 + j] = sigf(go_) * tanhfast(c);
        }
        __syncwarp();   // h2_new committed before next step reads it
    }

    // ---- final projection out[b] = h2 . Wout + bout ----
    const float wj = Wout[j];
    const float bo = bout[0];
#pragma unroll
    for (int e = 0; e < EPW; ++e) {
        float v = h2w[e * 32 + j] * wj;
#pragma unroll
        for (int off = 16; off; off >>= 1)
            v += __shfl_xor_sync(0xffffffffu, v, off);
        if (j == 0) out[eb + e] = v + bo;
    }
}

extern "C" void kernel_launch(void* const* d_in, const int* in_sizes, int n_in,
                              void* d_out, int out_size)
{
    const float* x    = (const float*)d_in[0];
    const float* Wih0 = (const float*)d_in[1];
    const float* Whh0 = (const float*)d_in[2];
    const float* bih0 = (const float*)d_in[3];
    const float* bhh0 = (const float*)d_in[4];
    const float* Wih1 = (const float*)d_in[5];
    const float* Whh1 = (const float*)d_in[6];
    const float* bih1 = (const float*)d_in[7];
    const float* bhh1 = (const float*)d_in[8];
    const float* Wout = (const float*)d_in[9];
    const float* bout = (const float*)d_in[10];
    float* out = (float*)d_out;

    const int B = out_size;                 // 4096
    const int T = in_sizes[0] / (B * DIN);  // 512

    cudaFuncSetAttribute(lstm2_kernel,
                         cudaFuncAttributeMaxDynamicSharedMemorySize, SM_BYTES);
    lstm2_kernel<<<B / ELB, NTHREADS, SM_BYTES>>>(
        x, Wih0, Whh0, bih0, bhh0, Wih1, Whh1, bih1, bhh1, Wout, bout, out, T);
}

// round 12
// speedup vs baseline: 3.5486x; 1.2594x over previous
#include <cuda_runtime.h>
#include <cuda_bf16.h>

// x is [B=4096, T=512, D=4] batch_first; H=32
#define DIN      4
#define EPW      4          // batch elements per warp-PAIR
#define NPAIR    8          // warp pairs per block
#define NTHREADS 512        // 16 warps
#define ELB      (NPAIR * EPW)   // 32 elements per block
#define CHUNK    16
#define WPAD     36         // padded weight row stride (floats)

typedef unsigned long long u64;

static __device__ __forceinline__ u64 pk2(float lo, float hi) {
    u64 r; asm("mov.b64 %0,{%1,%2};" : "=l"(r) : "f"(lo), "f"(hi)); return r;
}
static __device__ __forceinline__ void upk2(u64 v, float& lo, float& hi) {
    asm("mov.b64 {%0,%1},%2;" : "=f"(lo), "=f"(hi) : "l"(v));
}
static __device__ __forceinline__ u64 fma2(u64 a, u64 b, u64 c) {
    u64 d; asm("fma.rn.f32x2 %0,%1,%2,%3;" : "=l"(d) : "l"(a), "l"(b), "l"(c)); return d;
}
static __device__ __forceinline__ float sigf(float x) {
    return __fdividef(1.0f, 1.0f + __expf(-x));
}
static __device__ __forceinline__ float tanhfast(float x) {
    return __fdividef(2.0f, 1.0f + __expf(-2.0f * x)) - 1.0f;
}

// smem (floats): whh0|wih1|whh1 (128xWPAD each) | h1 | h2 | xbuf | gate-exchange
#define SM_FLOATS (3 * 128 * WPAD + 2 * NPAIR * EPW * 32 \
                   + NPAIR * EPW * CHUNK * 4 + NPAIR * EPW * 32 * 2)
#define SM_BYTES  (SM_FLOATS * 4)

__global__ __launch_bounds__(NTHREADS, 1)
void lstm2_kernel(const float* __restrict__ x,
                  const float* __restrict__ Wih0, const float* __restrict__ Whh0,
                  const float* __restrict__ bih0, const float* __restrict__ bhh0,
                  const float* __restrict__ Wih1, const float* __restrict__ Whh1,
                  const float* __restrict__ bih1, const float* __restrict__ bhh1,
                  const float* __restrict__ Wout, const float* __restrict__ bout,
                  float* __restrict__ out, int T)
{
    extern __shared__ float sm[];
    float* s_whh0 = sm;                           // [128][WPAD]
    float* s_wih1 = s_whh0 + 128 * WPAD;
    float* s_whh1 = s_wih1 + 128 * WPAD;
    float* s_h1   = s_whh1 + 128 * WPAD;          // [NPAIR][EPW][32]
    float* s_h2   = s_h1 + NPAIR * EPW * 32;
    float* s_x    = s_h2 + NPAIR * EPW * 32;      // [NPAIR][EPW][CHUNK][4]
    float* s_gx   = s_x + NPAIR * EPW * CHUNK * 4;// [NPAIR][EPW][32][2] {tanh_g, sig_o}

    const int tid  = threadIdx.x;
    const int w    = tid >> 5;
    const int j    = tid & 31;            // hidden unit owned by this lane
    const int pair = w >> 1;
    const int role = w & 1;               // 0: rows i,f (owns c/h)   1: rows g,o
    const int eb   = (blockIdx.x * NPAIR + pair) * EPW;
    const int T4   = T * DIN;

    // ---- stage recurrent/input weights into padded smem rows (once) ----
    for (int i = tid; i < 4096; i += NTHREADS) {
        int r = i >> 5, k = i & 31;
        s_whh0[r * WPAD + k] = Whh0[i];
        s_wih1[r * WPAD + k] = Wih1[i];
        s_whh1[r * WPAD + k] = Whh1[i];
    }

    float* h1w = s_h1 + pair * (EPW * 32);
    float* h2w = s_h2 + pair * (EPW * 32);
    float* xw  = s_x  + pair * (EPW * CHUNK * 4);
    float* gxw = s_gx + pair * (EPW * 64);

    if (role == 0) {
#pragma unroll
        for (int e = 0; e < EPW; ++e) { h1w[e * 32 + j] = 0.f; h2w[e * 32 + j] = 0.f; }
    }

    // this warp's two gate rows: role0 -> {i,f} = {j, 32+j}; role1 -> {g,o} = {64+j, 96+j}
    const int rA = role * 64 + j;
    const int rB = role * 64 + 32 + j;

    u64 wiA[2], wiB[2], b0A, b0B, b1A, b1B;
    {
        float4 wa = *(const float4*)(Wih0 + rA * 4);
        float4 wb = *(const float4*)(Wih0 + rB * 4);
        wiA[0] = pk2(wa.x, wa.y); wiA[1] = pk2(wa.z, wa.w);
        wiB[0] = pk2(wb.x, wb.y); wiB[1] = pk2(wb.z, wb.w);
        b0A = pk2(bih0[rA] + bhh0[rA], 0.f);
        b0B = pk2(bih0[rB] + bhh0[rB], 0.f);
        b1A = pk2(bih1[rA] + bhh1[rA], 0.f);
        b1B = pk2(bih1[rB] + bhh1[rB], 0.f);
    }

    const float wj = Wout[j];
    const float bo = bout[0];

    float c1[EPW], c2[EPW];
#pragma unroll
    for (int e = 0; e < EPW; ++e) { c1[e] = 0.f; c2[e] = 0.f; }

#define PAIRBAR() asm volatile("bar.sync %0, 64;" :: "r"(pair + 1) : "memory")

    __syncthreads();

    for (int t = 0; t < T; ++t) {
        // ---- stage x chunk (role 0 loads; pair barrier publishes) ----
        if ((t & (CHUNK - 1)) == 0) {
            if (role == 0) {
#pragma unroll
                for (int n = 0; n < (EPW * CHUNK) / 32; ++n) {  // 2 float4 per lane
                    int i  = n * 32 + j;           // float4 index: [el][tt]
                    int el = i >> 4;
                    int r  = i & (CHUNK - 1);
                    int tg = t + r;
                    float4 v = (tg < T)
                        ? *(const float4*)(x + (size_t)(eb + el) * T4 + tg * DIN)
                        : make_float4(0.f, 0.f, 0.f, 0.f);
                    *(float4*)(xw + i * 4) = v;
                }
            }
            PAIRBAR();
        }
        const int ts = t & (CHUNK - 1);

        // ================= layer 0 : this warp's 2 gate rows =================
        u64 accA[EPW], accB[EPW];
#pragma unroll
        for (int e = 0; e < EPW; ++e) {
            ulonglong2 xx = *(const ulonglong2*)(xw + e * (CHUNK * 4) + ts * 4);
            accA[e] = fma2(wiA[1], xx.y, fma2(wiA[0], xx.x, b0A));
            accB[e] = fma2(wiB[1], xx.y, fma2(wiB[0], xx.x, b0B));
        }
#pragma unroll
        for (int kk = 0; kk < 8; ++kk) {
            ulonglong2 wdA = *(const ulonglong2*)(s_whh0 + rA * WPAD + kk * 4);
            ulonglong2 wdB = *(const ulonglong2*)(s_whh0 + rB * WPAD + kk * 4);
#pragma unroll
            for (int e = 0; e < EPW; ++e) {
                ulonglong2 hh = *(const ulonglong2*)(h1w + e * 32 + kk * 4); // broadcast
                accA[e] = fma2(wdA.x, hh.x, accA[e]);
                accA[e] = fma2(wdA.y, hh.y, accA[e]);
                accB[e] = fma2(wdB.x, hh.x, accB[e]);
                accB[e] = fma2(wdB.y, hh.y, accB[e]);
            }
        }
        if (role == 1) {   // g,o: activate and publish
#pragma unroll
            for (int e = 0; e < EPW; ++e) {
                float lo, hi;
                upk2(accA[e], lo, hi); float g_ = lo + hi;
                upk2(accB[e], lo, hi); float o_ = lo + hi;
                *(float2*)(gxw + (e * 32 + j) * 2) =
                    make_float2(tanhfast(g_), sigf(o_));
            }
        }
        PAIRBAR();   // gates ready; also: all h1_old reads done
        if (role == 0) {   // i,f: update c, write h1
#pragma unroll
            for (int e = 0; e < EPW; ++e) {
                float lo, hi;
                upk2(accA[e], lo, hi); float i_ = lo + hi;
                upk2(accB[e], lo, hi); float f_ = lo + hi;
                float2 q = *(const float2*)(gxw + (e * 32 + j) * 2);
                float c = fmaf(sigf(f_), c1[e], sigf(i_) * q.x);
                c1[e] = c;
                h1w[e * 32 + j] = q.y * tanhfast(c);
            }
        }
        PAIRBAR();   // h1_new visible to both warps

        // ================= layer 1 =================
#pragma unroll
        for (int e = 0; e < EPW; ++e) { accA[e] = b1A; accB[e] = b1B; }
#pragma unroll
        for (int kk = 0; kk < 8; ++kk) {
            ulonglong2 wiAx = *(const ulonglong2*)(s_wih1 + rA * WPAD + kk * 4);
            ulonglong2 wiBx = *(const ulonglong2*)(s_wih1 + rB * WPAD + kk * 4);
            ulonglong2 whAx = *(const ulonglong2*)(s_whh1 + rA * WPAD + kk * 4);
            ulonglong2 whBx = *(const ulonglong2*)(s_whh1 + rB * WPAD + kk * 4);
#pragma unroll
            for (int e = 0; e < EPW; ++e) {
                ulonglong2 ha = *(const ulonglong2*)(h1w + e * 32 + kk * 4); // broadcast
                ulonglong2 hb = *(const ulonglong2*)(h2w + e * 32 + kk * 4); // broadcast
                accA[e] = fma2(wiAx.x, ha.x, accA[e]);
                accA[e] = fma2(wiAx.y, ha.y, accA[e]);
                accA[e] = fma2(whAx.x, hb.x, accA[e]);
                accA[e] = fma2(whAx.y, hb.y, accA[e]);
                accB[e] = fma2(wiBx.x, ha.x, accB[e]);
                accB[e] = fma2(wiBx.y, ha.y, accB[e]);
                accB[e] = fma2(whBx.x, hb.x, accB[e]);
                accB[e] = fma2(whBx.y, hb.y, accB[e]);
            }
        }
        if (role == 1) {
#pragma unroll
            for (int e = 0; e < EPW; ++e) {
                float lo, hi;
                upk2(accA[e], lo, hi); float g_ = lo + hi;
                upk2(accB[e], lo, hi); float o_ = lo + hi;
                *(float2*)(gxw + (e * 32 + j) * 2) =
                    make_float2(tanhfast(g_), sigf(o_));
            }
        }
        PAIRBAR();   // gates ready; all h2_old reads done
        if (role == 0) {
#pragma unroll
            for (int e = 0; e < EPW; ++e) {
                float lo, hi;
                upk2(accA[e], lo, hi); float i_ = lo + hi;
                upk2(accB[e], lo, hi); float f_ = lo + hi;
                float2 q = *(const float2*)(gxw + (e * 32 + j) * 2);
                float c = fmaf(sigf(f_), c2[e], sigf(i_) * q.x);
                c2[e] = c;
                h2w[e * 32 + j] = q.y * tanhfast(c);
            }
        }
        PAIRBAR();   // h2_new committed before next step reads it
    }

    // ---- final projection out[b] = h2 . Wout + bout (role-0 warps) ----
    if (role == 0) {
#pragma unroll
        for (int e = 0; e < EPW; ++e) {
            float v = h2w[e * 32 + j] * wj;
#pragma unroll
            for (int off = 16; off; off >>= 1)
                v += __shfl_xor_sync(0xffffffffu, v, off);
            if (j == 0) out[eb + e] = v + bo;
        }
    }
#undef PAIRBAR
}

extern "C" void kernel_launch(void* const* d_in, const int* in_sizes, int n_in,
                              void* d_out, int out_size)
{
    const float* x    = (const float*)d_in[0];
    const float* Wih0 = (const float*)d_in[1];
    const float* Whh0 = (const float*)d_in[2];
    const float* bih0 = (const float*)d_in[3];
    const float* bhh0 = (const float*)d_in[4];
    const float* Wih1 = (const float*)d_in[5];
    const float* Whh1 = (const float*)d_in[6];
    const float* bih1 = (const float*)d_in[7];
    const float* bhh1 = (const float*)d_in[8];
    const float* Wout = (const float*)d_in[9];
    const float* bout = (const float*)d_in[10];
    float* out = (float*)d_out;

    const int B = out_size;                 // 4096
    const int T = in_sizes[0] / (B * DIN);  // 512

    cudaFuncSetAttribute(lstm2_kernel,
                         cudaFuncAttributeMaxDynamicSharedMemorySize, SM_BYTES);
    lstm2_kernel<<<B / ELB, NTHREADS, SM_BYTES>>>(
        x, Wih0, Whh0, bih0, bhh0, Wih1, Whh1, bih1, bhh1, Wout, bout, out, T);
}